// round 1
// baseline (speedup 1.0000x reference)
#include <cuda_runtime.h>
#include <math.h>

// Problem shape (fixed by the dataset reference):
//   Q,K,V: [B=4, H=8, S=2048, Dh=64] fp32 ; src_batch_lens: [4] int32
//   out  : [4, 8, 2048, 64] fp32
// scores = (Q K^T) / sqrt(512); keys >= len[b] masked to -1e9 -> exp == 0
// exactly in fp32, so we skip them entirely (bit-equivalent).

#define B_    4
#define H_    8
#define S_    2048
#define DH    64
#define BM    128   // query rows per CTA (1 per thread)
#define BN    64    // key rows per smem tile

__global__ __launch_bounds__(BM)
void sdpa_fp32_kernel(const float* __restrict__ Q,
                      const float* __restrict__ K,
                      const float* __restrict__ V,
                      const int*   __restrict__ lens,
                      float*       __restrict__ out)
{
    const float SCALE = 0.044194173824159216f; // 1/sqrt(512)

    const int bh    = blockIdx.y;        // b*H + h
    const int b     = bh >> 3;           // H_ = 8
    const int qtile = blockIdx.x;
    const int tid   = threadIdx.x;
    const int L     = lens[b];           // 1..S

    const size_t base = (size_t)bh * S_ * DH;
    const float* Qbh = Q + base;
    const float* Kbh = K + base;
    const float* Vbh = V + base;
    float*       Obh = out + base;

    const int qrow = qtile * BM + tid;

    __shared__ float sK[BN * DH];
    __shared__ float sV[BN * DH];

    // Q row -> registers
    float4 q[DH / 4];
    {
        const float4* qp = (const float4*)(Qbh + (size_t)qrow * DH);
        #pragma unroll
        for (int i = 0; i < DH / 4; i++) q[i] = qp[i];
    }

    float4 acc[DH / 4];
    #pragma unroll
    for (int i = 0; i < DH / 4; i++) acc[i] = make_float4(0.f, 0.f, 0.f, 0.f);
    float m = -INFINITY;
    float l = 0.f;

    for (int k0 = 0; k0 < L; k0 += BN) {
        __syncthreads();   // previous tile fully consumed
        // load K/V tile: BN*DH floats = 1024 float4 each, 128 threads -> 8 apiece
        #pragma unroll
        for (int i = 0; i < (BN * DH / 4) / BM; i++) {
            int idx = tid + i * BM;          // float4 index
            int row = idx >> (6 - 2);        // DH/4 = 16 float4 per row
            int col = idx & 15;
            float4 kv = make_float4(0.f, 0.f, 0.f, 0.f);
            float4 vv = kv;
            if (k0 + row < L) {
                kv = ((const float4*)(Kbh + (size_t)(k0 + row) * DH))[col];
                vv = ((const float4*)(Vbh + (size_t)(k0 + row) * DH))[col];
            }
            ((float4*)sK)[idx] = kv;
            ((float4*)sV)[idx] = vv;
        }
        __syncthreads();

        const int jn = (L - k0 < BN) ? (L - k0) : BN;
        for (int j = 0; j < jn; j++) {
            // s = q . K[j]  (warp-uniform broadcast reads from smem)
            const float4* krow = (const float4*)(sK + j * DH);
            float s0 = 0.f, s1 = 0.f, s2 = 0.f, s3 = 0.f;
            #pragma unroll
            for (int i = 0; i < DH / 4; i++) {
                float4 kk = krow[i];
                s0 = fmaf(q[i].x, kk.x, s0);
                s1 = fmaf(q[i].y, kk.y, s1);
                s2 = fmaf(q[i].z, kk.z, s2);
                s3 = fmaf(q[i].w, kk.w, s3);
            }
            float s = ((s0 + s1) + (s2 + s3)) * SCALE;

            // lazy-rescale online softmax: max updates are O(log L) rare
            float p;
            if (s > m) {
                float c = __expf(m - s);   // exp(-inf)=0 on first key
                l = l * c + 1.f;
                #pragma unroll
                for (int i = 0; i < DH / 4; i++) {
                    acc[i].x *= c; acc[i].y *= c; acc[i].z *= c; acc[i].w *= c;
                }
                m = s;
                p = 1.f;
            } else {
                p = __expf(s - m);
                l += p;
            }

            const float4* vrow = (const float4*)(sV + j * DH);
            #pragma unroll
            for (int i = 0; i < DH / 4; i++) {
                float4 vv = vrow[i];
                acc[i].x = fmaf(p, vv.x, acc[i].x);
                acc[i].y = fmaf(p, vv.y, acc[i].y);
                acc[i].z = fmaf(p, vv.z, acc[i].z);
                acc[i].w = fmaf(p, vv.w, acc[i].w);
            }
        }
    }

    const float inv = 1.f / l;   // L >= 1 guaranteed -> l >= 1
    float4* op = (float4*)(Obh + (size_t)qrow * DH);
    #pragma unroll
    for (int i = 0; i < DH / 4; i++) {
        float4 a = acc[i];
        a.x *= inv; a.y *= inv; a.z *= inv; a.w *= inv;
        op[i] = a;
    }
}

extern "C" void kernel_launch(void* const* d_in, const int* in_sizes, int n_in,
                              void* d_out, int out_size)
{
    const float* Q    = (const float*)d_in[0];
    const float* K    = (const float*)d_in[1];
    const float* V    = (const float*)d_in[2];
    const int*   lens = (const int*)  d_in[3];
    float*       out  = (float*)d_out;

    dim3 grid(S_ / BM, B_ * H_);
    dim3 block(BM);
    sdpa_fp32_kernel<<<grid, block>>>(Q, K, V, lens, out);
}

// round 2
// speedup vs baseline: 1.0434x; 1.0434x over previous
#include <cuda_runtime.h>
#include <math.h>

// Q,K,V: [B=4, H=8, S=2048, Dh=64] fp32 ; src_batch_lens: [4] int32
// scores = (Q K^T)/sqrt(512); keys >= len[b] give exp==0 exactly -> skip them.

#define B_    4
#define H_    8
#define S_    2048
#define DH    64
#define BM    128   // query rows per CTA (1 per thread)
#define BN    64    // key rows per smem tile
#define CH    8     // keys per softmax chunk

__device__ __forceinline__ float ex2(float x) {
    float r;
    asm("ex2.approx.f32 %0, %1;" : "=f"(r) : "f"(x));
    return r;
}

__global__ __launch_bounds__(BM, 3)
void sdpa_fp32_kernel(const float* __restrict__ Q,
                      const float* __restrict__ K,
                      const float* __restrict__ V,
                      const int*   __restrict__ lens,
                      float*       __restrict__ out)
{
    // 1/sqrt(512) * log2(e): scores kept in log2 domain, ex2 for exp
    const float SCALE2 = 0.044194173824159216f * 1.4426950408889634f;

    const int bh    = blockIdx.y;
    const int b     = bh >> 3;
    const int qtile = blockIdx.x;
    const int tid   = threadIdx.x;
    const int L     = lens[b];

    const size_t base = (size_t)bh * S_ * DH;
    const float* Qbh = Q + base;
    const float* Kbh = K + base;
    const float* Vbh = V + base;
    float*       Obh = out + base;

    const int qrow = qtile * BM + tid;

    __shared__ float sK[BN * DH];
    __shared__ float sV[BN * DH];

    float4 q[DH / 4];
    {
        const float4* qp = (const float4*)(Qbh + (size_t)qrow * DH);
        #pragma unroll
        for (int i = 0; i < DH / 4; i++) q[i] = qp[i];
    }

    float4 acc[DH / 4];
    #pragma unroll
    for (int i = 0; i < DH / 4; i++) acc[i] = make_float4(0.f, 0.f, 0.f, 0.f);
    float m = -INFINITY;
    float l = 0.f;

    for (int k0 = 0; k0 < L; k0 += BN) {
        __syncthreads();
        #pragma unroll
        for (int i = 0; i < (BN * DH / 4) / BM; i++) {
            int idx = tid + i * BM;
            int row = idx >> 4;          // DH/4 = 16 float4 per row
            int col = idx & 15;
            float4 kv = make_float4(0.f, 0.f, 0.f, 0.f);
            float4 vv = kv;
            if (k0 + row < L) {
                kv = ((const float4*)(Kbh + (size_t)(k0 + row) * DH))[col];
                vv = ((const float4*)(Vbh + (size_t)(k0 + row) * DH))[col];
            }
            ((float4*)sK)[idx] = kv;
            ((float4*)sV)[idx] = vv;
        }
        __syncthreads();

        const int jn = (L - k0 < BN) ? (L - k0) : BN;
        int j = 0;

        // ---- full chunks of CH keys ----
        for (; j + CH <= jn; j += CH) {
            float sc[CH];
            #pragma unroll
            for (int u = 0; u < CH; u++) {
                const float4* krow = (const float4*)(sK + (j + u) * DH);
                float s0 = 0.f, s1 = 0.f, s2 = 0.f, s3 = 0.f;
                #pragma unroll
                for (int i = 0; i < DH / 4; i++) {
                    float4 kk = krow[i];
                    s0 = fmaf(q[i].x, kk.x, s0);
                    s1 = fmaf(q[i].y, kk.y, s1);
                    s2 = fmaf(q[i].z, kk.z, s2);
                    s3 = fmaf(q[i].w, kk.w, s3);
                }
                sc[u] = ((s0 + s1) + (s2 + s3)) * SCALE2;
            }

            float cm = sc[0];
            #pragma unroll
            for (int u = 1; u < CH; u++) cm = fmaxf(cm, sc[u]);

            if (cm > m) {                      // rare after warm-up
                float c = ex2(m - cm);         // ex2(-inf)=0 on first chunk
                l *= c;
                #pragma unroll
                for (int i = 0; i < DH / 4; i++) {
                    acc[i].x *= c; acc[i].y *= c; acc[i].z *= c; acc[i].w *= c;
                }
                m = cm;
            }

            float p[CH];
            #pragma unroll
            for (int u = 0; u < CH; u++) {     // 8 independent MUFU.EX2
                p[u] = ex2(sc[u] - m);
                l += p[u];
            }

            #pragma unroll
            for (int u = 0; u < CH; u++) {
                const float4* vrow = (const float4*)(sV + (j + u) * DH);
                float pu = p[u];
                #pragma unroll
                for (int i = 0; i < DH / 4; i++) {
                    float4 vv = vrow[i];
                    acc[i].x = fmaf(pu, vv.x, acc[i].x);
                    acc[i].y = fmaf(pu, vv.y, acc[i].y);
                    acc[i].z = fmaf(pu, vv.z, acc[i].z);
                    acc[i].w = fmaf(pu, vv.w, acc[i].w);
                }
            }
        }

        // ---- scalar tail (last partial chunk of last tile only) ----
        for (; j < jn; j++) {
            const float4* krow = (const float4*)(sK + j * DH);
            float s0 = 0.f, s1 = 0.f, s2 = 0.f, s3 = 0.f;
            #pragma unroll
            for (int i = 0; i < DH / 4; i++) {
                float4 kk = krow[i];
                s0 = fmaf(q[i].x, kk.x, s0);
                s1 = fmaf(q[i].y, kk.y, s1);
                s2 = fmaf(q[i].z, kk.z, s2);
                s3 = fmaf(q[i].w, kk.w, s3);
            }
            float s = ((s0 + s1) + (s2 + s3)) * SCALE2;

            float p;
            if (s > m) {
                float c = ex2(m - s);
                l = l * c + 1.f;
                #pragma unroll
                for (int i = 0; i < DH / 4; i++) {
                    acc[i].x *= c; acc[i].y *= c; acc[i].z *= c; acc[i].w *= c;
                }
                m = s;
                p = 1.f;
            } else {
                p = ex2(s - m);
                l += p;
            }
            const float4* vrow = (const float4*)(sV + j * DH);
            #pragma unroll
            for (int i = 0; i < DH / 4; i++) {
                float4 vv = vrow[i];
                acc[i].x = fmaf(p, vv.x, acc[i].x);
                acc[i].y = fmaf(p, vv.y, acc[i].y);
                acc[i].z = fmaf(p, vv.z, acc[i].z);
                acc[i].w = fmaf(p, vv.w, acc[i].w);
            }
        }
    }

    const float inv = 1.f / l;
    float4* op = (float4*)(Obh + (size_t)qrow * DH);
    #pragma unroll
    for (int i = 0; i < DH / 4; i++) {
        float4 a = acc[i];
        a.x *= inv; a.y *= inv; a.z *= inv; a.w *= inv;
        op[i] = a;
    }
}

extern "C" void kernel_launch(void* const* d_in, const int* in_sizes, int n_in,
                              void* d_out, int out_size)
{
    const float* Q    = (const float*)d_in[0];
    const float* K    = (const float*)d_in[1];
    const float* V    = (const float*)d_in[2];
    const int*   lens = (const int*)  d_in[3];
    float*       out  = (float*)d_out;

    dim3 grid(S_ / BM, B_ * H_);
    dim3 block(BM);
    sdpa_fp32_kernel<<<grid, block>>>(Q, K, V, lens, out);
}

// round 3
// speedup vs baseline: 2.2580x; 2.1642x over previous
#include <cuda_runtime.h>
#include <math.h>
#include <stdint.h>

// Q,K,V: [B=4, H=8, S=2048, Dh=64] fp32 ; src_batch_lens: [4] int32
// Flash attention, warp-tiled, mma.sync m16n8k8 tf32.
// QK^T uses 3-term split-tf32 (~fp32 accuracy); PV plain tf32.

#define B_    4
#define H_    8
#define S_    2048
#define DH    64
#define BM    64    // q rows per CTA (16 per warp)
#define BN    64    // keys per smem tile
#define KSTR  68    // sK row stride in floats (conflict-free for QK B-frags)
#define VSTR  72    // sV row stride in floats (conflict-free for PV B-frags)

__device__ __forceinline__ float ex2f(float x) {
    float r; asm("ex2.approx.f32 %0, %1;" : "=f"(r) : "f"(x)); return r;
}
__device__ __forceinline__ uint32_t f2tf(float x) {
    uint32_t r; asm("cvt.rna.tf32.f32 %0, %1;" : "=r"(r) : "f"(x)); return r;
}
__device__ __forceinline__ void split_tf(float v, uint32_t& h, uint32_t& l) {
    h = f2tf(v);
    l = f2tf(v - __uint_as_float(h));
}
__device__ __forceinline__ void mma_tf32(float d[4], const uint32_t a[4],
                                         const uint32_t b[2], const float c[4]) {
    asm("mma.sync.aligned.m16n8k8.row.col.f32.tf32.tf32.f32 "
        "{%0,%1,%2,%3},{%4,%5,%6,%7},{%8,%9},{%10,%11,%12,%13};"
        : "=f"(d[0]), "=f"(d[1]), "=f"(d[2]), "=f"(d[3])
        : "r"(a[0]), "r"(a[1]), "r"(a[2]), "r"(a[3]),
          "r"(b[0]), "r"(b[1]),
          "f"(c[0]), "f"(c[1]), "f"(c[2]), "f"(c[3]));
}

__global__ __launch_bounds__(128)
void sdpa_tf32_kernel(const float* __restrict__ Q,
                      const float* __restrict__ K,
                      const float* __restrict__ V,
                      const int*   __restrict__ lens,
                      float*       __restrict__ out)
{
    // 1/sqrt(512) * log2(e): keep scores in log2 domain, use ex2
    const float SCALE2 = 0.044194173824159216f * 1.4426950408889634f;

    const int bh    = blockIdx.y;
    const int b     = bh >> 3;
    const int qtile = blockIdx.x;
    const int tid   = threadIdx.x;
    const int warp  = tid >> 5;
    const int lane  = tid & 31;
    const int g     = lane >> 2;    // group id: row offset
    const int j     = lane & 3;     // thread-in-group
    const int L     = lens[b];

    const size_t base = (size_t)bh * S_ * DH;
    const float* Qbh = Q + base;
    const float* Kbh = K + base;
    const float* Vbh = V + base;
    float*       Obh = out + base;

    __shared__ float sK[BN * KSTR];
    __shared__ float sV[BN * VSTR];

    // ---- stage Q tile [BM x DH] through sK, read A-fragments (hi/lo split) ----
    #pragma unroll
    for (int i = 0; i < 8; i++) {
        int idx = tid + i * 128;            // float4 index, 1024 total
        int row = idx >> 4;
        int c4  = idx & 15;
        *(float4*)(sK + row * KSTR + c4 * 4) =
            ((const float4*)(Qbh + (size_t)(qtile * BM + row) * DH))[c4];
    }
    __syncthreads();

    uint32_t qhi[8][4], qlo[8][4];
    {
        const float* qb = sK + (warp * 16) * KSTR;
        #pragma unroll
        for (int ks = 0; ks < 8; ks++) {
            split_tf(qb[g       * KSTR + ks * 8 + j    ], qhi[ks][0], qlo[ks][0]);
            split_tf(qb[(g + 8) * KSTR + ks * 8 + j    ], qhi[ks][1], qlo[ks][1]);
            split_tf(qb[g       * KSTR + ks * 8 + j + 4], qhi[ks][2], qlo[ks][2]);
            split_tf(qb[(g + 8) * KSTR + ks * 8 + j + 4], qhi[ks][3], qlo[ks][3]);
        }
    }
    __syncthreads();

    float O[8][4];
    #pragma unroll
    for (int dt = 0; dt < 8; dt++)
        #pragma unroll
        for (int e = 0; e < 4; e++) O[dt][e] = 0.f;
    float m0 = -INFINITY, m1 = -INFINITY;
    float l0 = 0.f, l1 = 0.f;

    const int src0 = (lane & ~3) | (j >> 1);  // 4g + j/2
    const int src2 = src0 + 2;

    for (int k0 = 0; k0 < L; k0 += BN) {
        __syncthreads();
        #pragma unroll
        for (int i = 0; i < 8; i++) {
            int idx = tid + i * 128;
            int row = idx >> 4;
            int c4  = idx & 15;
            float4 kv = make_float4(0.f, 0.f, 0.f, 0.f);
            float4 vv = kv;
            if (k0 + row < L) {
                kv = ((const float4*)(Kbh + (size_t)(k0 + row) * DH))[c4];
                vv = ((const float4*)(Vbh + (size_t)(k0 + row) * DH))[c4];
            }
            *(float4*)(sK + row * KSTR + c4 * 4) = kv;
            *(float4*)(sV + row * VSTR + c4 * 4) = vv;
        }
        __syncthreads();

        // ---- S = Q K^T  (3x split-tf32) ----
        float Sacc[8][4];
        #pragma unroll
        for (int nt = 0; nt < 8; nt++)
            #pragma unroll
            for (int e = 0; e < 4; e++) Sacc[nt][e] = 0.f;

        #pragma unroll
        for (int ks = 0; ks < 8; ks++) {
            #pragma unroll
            for (int nt = 0; nt < 8; nt++) {
                float k0f = sK[(nt * 8 + g) * KSTR + ks * 8 + j];
                float k1f = sK[(nt * 8 + g) * KSTR + ks * 8 + j + 4];
                uint32_t bhf[2], blf[2];
                split_tf(k0f, bhf[0], blf[0]);
                split_tf(k1f, bhf[1], blf[1]);
                mma_tf32(Sacc[nt], qhi[ks], bhf, Sacc[nt]);
                mma_tf32(Sacc[nt], qhi[ks], blf, Sacc[nt]);
                mma_tf32(Sacc[nt], qlo[ks], bhf, Sacc[nt]);
            }
        }

        // scale to log2 domain
        #pragma unroll
        for (int nt = 0; nt < 8; nt++)
            #pragma unroll
            for (int e = 0; e < 4; e++) Sacc[nt][e] *= SCALE2;

        // mask invalid keys in a partial final tile
        if (k0 + BN > L) {
            #pragma unroll
            for (int nt = 0; nt < 8; nt++) {
                int col0 = k0 + nt * 8 + 2 * j;
                if (col0     >= L) { Sacc[nt][0] = -1e30f; Sacc[nt][2] = -1e30f; }
                if (col0 + 1 >= L) { Sacc[nt][1] = -1e30f; Sacc[nt][3] = -1e30f; }
            }
        }

        // ---- online softmax ----
        float cm0 = Sacc[0][0], cm1 = Sacc[0][2];
        #pragma unroll
        for (int nt = 0; nt < 8; nt++) {
            cm0 = fmaxf(cm0, fmaxf(Sacc[nt][0], Sacc[nt][1]));
            cm1 = fmaxf(cm1, fmaxf(Sacc[nt][2], Sacc[nt][3]));
        }
        cm0 = fmaxf(cm0, __shfl_xor_sync(0xffffffffu, cm0, 1));
        cm0 = fmaxf(cm0, __shfl_xor_sync(0xffffffffu, cm0, 2));
        cm1 = fmaxf(cm1, __shfl_xor_sync(0xffffffffu, cm1, 1));
        cm1 = fmaxf(cm1, __shfl_xor_sync(0xffffffffu, cm1, 2));

        float mn0 = fmaxf(m0, cm0);
        float mn1 = fmaxf(m1, cm1);
        float sc0 = ex2f(m0 - mn0);   // first tile: ex2(-inf)=0
        float sc1 = ex2f(m1 - mn1);
        m0 = mn0; m1 = mn1;
        l0 *= sc0; l1 *= sc1;
        #pragma unroll
        for (int dt = 0; dt < 8; dt++) {
            O[dt][0] *= sc0; O[dt][1] *= sc0;
            O[dt][2] *= sc1; O[dt][3] *= sc1;
        }

        // p = ex2(s - m), build P A-fragments via shuffles
        uint32_t aP[8][4];
        #pragma unroll
        for (int nt = 0; nt < 8; nt++) {
            float p0 = ex2f(Sacc[nt][0] - m0);
            float p1 = ex2f(Sacc[nt][1] - m0);
            float p2 = ex2f(Sacc[nt][2] - m1);
            float p3 = ex2f(Sacc[nt][3] - m1);
            l0 += p0 + p1;
            l1 += p2 + p3;

            float v0, v1;
            v0 = __shfl_sync(0xffffffffu, p0, src0);
            v1 = __shfl_sync(0xffffffffu, p1, src0);
            float f0 = (j & 1) ? v1 : v0;
            v0 = __shfl_sync(0xffffffffu, p2, src0);
            v1 = __shfl_sync(0xffffffffu, p3, src0);
            float f1 = (j & 1) ? v1 : v0;
            v0 = __shfl_sync(0xffffffffu, p0, src2);
            v1 = __shfl_sync(0xffffffffu, p1, src2);
            float f2 = (j & 1) ? v1 : v0;
            v0 = __shfl_sync(0xffffffffu, p2, src2);
            v1 = __shfl_sync(0xffffffffu, p3, src2);
            float f3 = (j & 1) ? v1 : v0;

            aP[nt][0] = f2tf(f0);
            aP[nt][1] = f2tf(f1);
            aP[nt][2] = f2tf(f2);
            aP[nt][3] = f2tf(f3);
        }

        // ---- O += P V ----
        #pragma unroll
        for (int dt = 0; dt < 8; dt++) {
            #pragma unroll
            for (int ks = 0; ks < 8; ks++) {
                uint32_t bb[2];
                bb[0] = f2tf(sV[(ks * 8 + j    ) * VSTR + dt * 8 + g]);
                bb[1] = f2tf(sV[(ks * 8 + j + 4) * VSTR + dt * 8 + g]);
                mma_tf32(O[dt], aP[ks], bb, O[dt]);
            }
        }
    }

    // ---- epilogue ----
    l0 += __shfl_xor_sync(0xffffffffu, l0, 1);
    l0 += __shfl_xor_sync(0xffffffffu, l0, 2);
    l1 += __shfl_xor_sync(0xffffffffu, l1, 1);
    l1 += __shfl_xor_sync(0xffffffffu, l1, 2);
    float inv0 = 1.f / l0;
    float inv1 = 1.f / l1;

    const int qrow0 = qtile * BM + warp * 16;
    #pragma unroll
    for (int dt = 0; dt < 8; dt++) {
        int col = dt * 8 + 2 * j;
        float2 r0 = make_float2(O[dt][0] * inv0, O[dt][1] * inv0);
        float2 r1 = make_float2(O[dt][2] * inv1, O[dt][3] * inv1);
        *(float2*)(Obh + (size_t)(qrow0 + g    ) * DH + col) = r0;
        *(float2*)(Obh + (size_t)(qrow0 + g + 8) * DH + col) = r1;
    }
}

extern "C" void kernel_launch(void* const* d_in, const int* in_sizes, int n_in,
                              void* d_out, int out_size)
{
    const float* Q    = (const float*)d_in[0];
    const float* K    = (const float*)d_in[1];
    const float* V    = (const float*)d_in[2];
    const int*   lens = (const int*)  d_in[3];
    float*       out  = (float*)d_out;

    dim3 grid(S_ / BM, B_ * H_);
    dim3 block(128);
    sdpa_tf32_kernel<<<grid, block>>>(Q, K, V, lens, out);
}

// round 4
// speedup vs baseline: 2.4857x; 1.1008x over previous
#include <cuda_runtime.h>
#include <math.h>
#include <stdint.h>

// Q,K,V: [B=4, H=8, S=2048, Dh=64] fp32 ; src_batch_lens: [4] int32
// Flash attention, warp-tiled, mma.sync m16n8k8 tf32.
// QK^T: 3-term split-tf32 (~fp32 accuracy); PV plain tf32.
// K split + V convert done ONCE per CTA at tile load; P staged via smem.

#define B_    4
#define H_    8
#define S_    2048
#define DH    64
#define BM    64    // q rows per CTA (16 per warp)
#define BN    64    // keys per smem tile
#define KSTR  68    // sKhi/sKlo row stride (words) — (4g+j)%32 distinct
#define VSTR  72    // sV row stride (words)       — (8j+g)%32 distinct

#define SMEM_WORDS (2 * BN * KSTR + BN * VSTR)
#define SMEM_BYTES (SMEM_WORDS * 4)

__device__ __forceinline__ float ex2f(float x) {
    float r; asm("ex2.approx.f32 %0, %1;" : "=f"(r) : "f"(x)); return r;
}
__device__ __forceinline__ uint32_t f2tf(float x) {
    uint32_t r; asm("cvt.rna.tf32.f32 %0, %1;" : "=r"(r) : "f"(x)); return r;
}
__device__ __forceinline__ void split_tf(float v, uint32_t& h, uint32_t& l) {
    h = f2tf(v);
    l = f2tf(v - __uint_as_float(h));
}
__device__ __forceinline__ void mma_tf32(float d[4], const uint32_t a[4],
                                         const uint32_t b[2], const float c[4]) {
    asm("mma.sync.aligned.m16n8k8.row.col.f32.tf32.tf32.f32 "
        "{%0,%1,%2,%3},{%4,%5,%6,%7},{%8,%9},{%10,%11,%12,%13};"
        : "=f"(d[0]), "=f"(d[1]), "=f"(d[2]), "=f"(d[3])
        : "r"(a[0]), "r"(a[1]), "r"(a[2]), "r"(a[3]),
          "r"(b[0]), "r"(b[1]),
          "f"(c[0]), "f"(c[1]), "f"(c[2]), "f"(c[3]));
}

__global__ __launch_bounds__(128)
void sdpa_tf32_kernel(const float* __restrict__ Q,
                      const float* __restrict__ K,
                      const float* __restrict__ V,
                      const int*   __restrict__ lens,
                      float*       __restrict__ out)
{
    const float SCALE2 = 0.044194173824159216f * 1.4426950408889634f; // /sqrt(512)*log2e

    const int bh    = blockIdx.y;
    const int b     = bh >> 3;
    const int qtile = blockIdx.x;
    const int tid   = threadIdx.x;
    const int warp  = tid >> 5;
    const int lane  = tid & 31;
    const int g     = lane >> 2;
    const int j     = lane & 3;
    const int L     = lens[b];

    const size_t base = (size_t)bh * S_ * DH;
    const float* Qbh = Q + base;
    const float* Kbh = K + base;
    const float* Vbh = V + base;
    float*       Obh = out + base;

    extern __shared__ uint32_t smemraw[];
    uint32_t* sKhi = smemraw;                 // BN*KSTR ; doubles as Q stage + P stage
    uint32_t* sKlo = sKhi + BN * KSTR;        // BN*KSTR
    uint32_t* sV   = sKlo + BN * KSTR;        // BN*VSTR

    // ---- stage Q tile through sKhi (as raw float bits), split to regs ----
    #pragma unroll
    for (int i = 0; i < 8; i++) {
        int idx = tid + i * 128;
        int row = idx >> 4;
        int c4  = idx & 15;
        float4 qv = ((const float4*)(Qbh + (size_t)(qtile * BM + row) * DH))[c4];
        *(float4*)((float*)sKhi + row * KSTR + c4 * 4) = qv;
    }
    __syncthreads();

    uint32_t qhi[8][4], qlo[8][4];
    {
        const float* qb = (const float*)sKhi + (warp * 16) * KSTR;
        #pragma unroll
        for (int ks = 0; ks < 8; ks++) {
            split_tf(qb[g       * KSTR + ks * 8 + j    ], qhi[ks][0], qlo[ks][0]);
            split_tf(qb[(g + 8) * KSTR + ks * 8 + j    ], qhi[ks][1], qlo[ks][1]);
            split_tf(qb[g       * KSTR + ks * 8 + j + 4], qhi[ks][2], qlo[ks][2]);
            split_tf(qb[(g + 8) * KSTR + ks * 8 + j + 4], qhi[ks][3], qlo[ks][3]);
        }
    }

    float O[8][4];
    #pragma unroll
    for (int dt = 0; dt < 8; dt++)
        #pragma unroll
        for (int e = 0; e < 4; e++) O[dt][e] = 0.f;
    float m0 = -INFINITY, m1 = -INFINITY;
    float l0 = 0.f, l1 = 0.f;

    uint32_t* pw = sKhi + (warp * 16) * KSTR;   // this warp's private P slice

    for (int k0 = 0; k0 < L; k0 += BN) {
        __syncthreads();   // prev tile: PV done reading sV & P (and Q stage done)
        // ---- load tile: split K -> (hi,lo) tf32, convert V -> tf32, ONCE ----
        #pragma unroll
        for (int i = 0; i < 8; i++) {
            int idx = tid + i * 128;
            int row = idx >> 4;
            int c4  = idx & 15;
            float4 kv = make_float4(0.f, 0.f, 0.f, 0.f);
            float4 vv = kv;
            if (k0 + row < L) {
                kv = ((const float4*)(Kbh + (size_t)(k0 + row) * DH))[c4];
                vv = ((const float4*)(Vbh + (size_t)(k0 + row) * DH))[c4];
            }
            uint4 kh, kl, vt;
            split_tf(kv.x, kh.x, kl.x); split_tf(kv.y, kh.y, kl.y);
            split_tf(kv.z, kh.z, kl.z); split_tf(kv.w, kh.w, kl.w);
            vt.x = f2tf(vv.x); vt.y = f2tf(vv.y);
            vt.z = f2tf(vv.z); vt.w = f2tf(vv.w);
            *(uint4*)(sKhi + row * KSTR + c4 * 4) = kh;
            *(uint4*)(sKlo + row * KSTR + c4 * 4) = kl;
            *(uint4*)(sV   + row * VSTR + c4 * 4) = vt;
        }
        __syncthreads();

        // ---- S = Q K^T (3-term split-tf32) ----
        float Sacc[8][4];
        #pragma unroll
        for (int nt = 0; nt < 8; nt++)
            #pragma unroll
            for (int e = 0; e < 4; e++) Sacc[nt][e] = 0.f;

        #pragma unroll
        for (int ks = 0; ks < 8; ks++) {
            #pragma unroll
            for (int nt = 0; nt < 8; nt++) {
                const int r = (nt * 8 + g) * KSTR + ks * 8 + j;
                uint32_t bhf[2] = { sKhi[r], sKhi[r + 4] };
                uint32_t blf[2] = { sKlo[r], sKlo[r + 4] };
                mma_tf32(Sacc[nt], qhi[ks], bhf, Sacc[nt]);
                mma_tf32(Sacc[nt], qhi[ks], blf, Sacc[nt]);
                mma_tf32(Sacc[nt], qlo[ks], bhf, Sacc[nt]);
            }
        }

        #pragma unroll
        for (int nt = 0; nt < 8; nt++)
            #pragma unroll
            for (int e = 0; e < 4; e++) Sacc[nt][e] *= SCALE2;

        if (k0 + BN > L) {
            #pragma unroll
            for (int nt = 0; nt < 8; nt++) {
                int col0 = k0 + nt * 8 + 2 * j;
                if (col0     >= L) { Sacc[nt][0] = -1e30f; Sacc[nt][2] = -1e30f; }
                if (col0 + 1 >= L) { Sacc[nt][1] = -1e30f; Sacc[nt][3] = -1e30f; }
            }
        }

        // ---- online softmax ----
        float cm0 = Sacc[0][0], cm1 = Sacc[0][2];
        #pragma unroll
        for (int nt = 0; nt < 8; nt++) {
            cm0 = fmaxf(cm0, fmaxf(Sacc[nt][0], Sacc[nt][1]));
            cm1 = fmaxf(cm1, fmaxf(Sacc[nt][2], Sacc[nt][3]));
        }
        cm0 = fmaxf(cm0, __shfl_xor_sync(0xffffffffu, cm0, 1));
        cm0 = fmaxf(cm0, __shfl_xor_sync(0xffffffffu, cm0, 2));
        cm1 = fmaxf(cm1, __shfl_xor_sync(0xffffffffu, cm1, 1));
        cm1 = fmaxf(cm1, __shfl_xor_sync(0xffffffffu, cm1, 2));

        float mn0 = fmaxf(m0, cm0);
        float mn1 = fmaxf(m1, cm1);
        float sc0 = ex2f(m0 - mn0);   // first tile: ex2(-inf)=0
        float sc1 = ex2f(m1 - mn1);
        m0 = mn0; m1 = mn1;
        l0 *= sc0; l1 *= sc1;
        #pragma unroll
        for (int dt = 0; dt < 8; dt++) {
            O[dt][0] *= sc0; O[dt][1] *= sc0;
            O[dt][2] *= sc1; O[dt][3] *= sc1;
        }

        __syncthreads();   // all warps finished reading sKhi/sKlo for QK

        // ---- p = ex2(s-m): write tf32 P into this warp's smem slice ----
        #pragma unroll
        for (int nt = 0; nt < 8; nt++) {
            float p0 = ex2f(Sacc[nt][0] - m0);
            float p1 = ex2f(Sacc[nt][1] - m0);
            float p2 = ex2f(Sacc[nt][2] - m1);
            float p3 = ex2f(Sacc[nt][3] - m1);
            l0 += p0 + p1;
            l1 += p2 + p3;
            *(uint2*)(pw + g       * KSTR + nt * 8 + 2 * j) =
                make_uint2(f2tf(p0), f2tf(p1));
            *(uint2*)(pw + (g + 8) * KSTR + nt * 8 + 2 * j) =
                make_uint2(f2tf(p2), f2tf(p3));
        }
        __syncwarp();

        // ---- O += P V ----
        #pragma unroll
        for (int ks = 0; ks < 8; ks++) {
            const int pr = g * KSTR + ks * 8 + j;
            uint32_t a[4] = { pw[pr], pw[pr + 8 * KSTR],
                              pw[pr + 4], pw[pr + 8 * KSTR + 4] };
            #pragma unroll
            for (int dt = 0; dt < 8; dt++) {
                uint32_t bb[2] = { sV[(ks * 8 + j    ) * VSTR + dt * 8 + g],
                                   sV[(ks * 8 + j + 4) * VSTR + dt * 8 + g] };
                mma_tf32(O[dt], a, bb, O[dt]);
            }
        }
    }

    // ---- epilogue ----
    l0 += __shfl_xor_sync(0xffffffffu, l0, 1);
    l0 += __shfl_xor_sync(0xffffffffu, l0, 2);
    l1 += __shfl_xor_sync(0xffffffffu, l1, 1);
    l1 += __shfl_xor_sync(0xffffffffu, l1, 2);
    float inv0 = 1.f / l0;
    float inv1 = 1.f / l1;

    const int qrow0 = qtile * BM + warp * 16;
    #pragma unroll
    for (int dt = 0; dt < 8; dt++) {
        int col = dt * 8 + 2 * j;
        float2 r0 = make_float2(O[dt][0] * inv0, O[dt][1] * inv0);
        float2 r1 = make_float2(O[dt][2] * inv1, O[dt][3] * inv1);
        *(float2*)(Obh + (size_t)(qrow0 + g    ) * DH + col) = r0;
        *(float2*)(Obh + (size_t)(qrow0 + g + 8) * DH + col) = r1;
    }
}

extern "C" void kernel_launch(void* const* d_in, const int* in_sizes, int n_in,
                              void* d_out, int out_size)
{
    const float* Q    = (const float*)d_in[0];
    const float* K    = (const float*)d_in[1];
    const float* V    = (const float*)d_in[2];
    const int*   lens = (const int*)  d_in[3];
    float*       out  = (float*)d_out;

    cudaFuncSetAttribute(sdpa_tf32_kernel,
                         cudaFuncAttributeMaxDynamicSharedMemorySize, SMEM_BYTES);

    dim3 grid(S_ / BM, B_ * H_);
    dim3 block(128);
    sdpa_tf32_kernel<<<grid, block, SMEM_BYTES>>>(Q, K, V, lens, out);
}

// round 5
// speedup vs baseline: 2.4860x; 1.0001x over previous
#include <cuda_runtime.h>
#include <math.h>
#include <stdint.h>

// Q,K,V: [B=4, H=8, S=2048, Dh=64] fp32 ; src_batch_lens: [4] int32
// Flash attention, warp-tiled, mma.sync m16n8k8 tf32.
// QK^T: 3-term split-tf32 (~fp32 accuracy); PV plain tf32.
// K split + V convert done ONCE per CTA at tile load; P staged via smem.

#define B_    4
#define H_    8
#define S_    2048
#define DH    64
#define BM    64    // q rows per CTA (16 per warp)
#define BN    64    // keys per smem tile
#define KSTR  68    // sKhi/sKlo row stride (words) — (4g+j)%32 distinct
#define VSTR  72    // sV row stride (words)       — (8j+g)%32 distinct

#define SMEM_WORDS (2 * BN * KSTR + BN * VSTR)
#define SMEM_BYTES (SMEM_WORDS * 4)

__device__ __forceinline__ float ex2f(float x) {
    float r; asm("ex2.approx.f32 %0, %1;" : "=f"(r) : "f"(x)); return r;
}
__device__ __forceinline__ uint32_t f2tf(float x) {
    uint32_t r; asm("cvt.rna.tf32.f32 %0, %1;" : "=r"(r) : "f"(x)); return r;
}
__device__ __forceinline__ void split_tf(float v, uint32_t& h, uint32_t& l) {
    h = f2tf(v);
    l = f2tf(v - __uint_as_float(h));
}
__device__ __forceinline__ void mma_tf32(float d[4], const uint32_t a[4],
                                         const uint32_t b[2], const float c[4]) {
    asm("mma.sync.aligned.m16n8k8.row.col.f32.tf32.tf32.f32 "
        "{%0,%1,%2,%3},{%4,%5,%6,%7},{%8,%9},{%10,%11,%12,%13};"
        : "=f"(d[0]), "=f"(d[1]), "=f"(d[2]), "=f"(d[3])
        : "r"(a[0]), "r"(a[1]), "r"(a[2]), "r"(a[3]),
          "r"(b[0]), "r"(b[1]),
          "f"(c[0]), "f"(c[1]), "f"(c[2]), "f"(c[3]));
}

__global__ __launch_bounds__(128)
void sdpa_tf32_kernel(const float* __restrict__ Q,
                      const float* __restrict__ K,
                      const float* __restrict__ V,
                      const int*   __restrict__ lens,
                      float*       __restrict__ out)
{
    const float SCALE2 = 0.044194173824159216f * 1.4426950408889634f; // /sqrt(512)*log2e

    const int bh    = blockIdx.y;
    const int b     = bh >> 3;
    const int qtile = blockIdx.x;
    const int tid   = threadIdx.x;
    const int warp  = tid >> 5;
    const int lane  = tid & 31;
    const int g     = lane >> 2;
    const int j     = lane & 3;
    const int L     = lens[b];

    const size_t base = (size_t)bh * S_ * DH;
    const float* Qbh = Q + base;
    const float* Kbh = K + base;
    const float* Vbh = V + base;
    float*       Obh = out + base;

    extern __shared__ uint32_t smemraw[];
    uint32_t* sKhi = smemraw;                 // BN*KSTR ; doubles as Q stage + P stage
    uint32_t* sKlo = sKhi + BN * KSTR;        // BN*KSTR
    uint32_t* sV   = sKlo + BN * KSTR;        // BN*VSTR

    // ---- stage Q tile through sKhi (as raw float bits), split to regs ----
    #pragma unroll
    for (int i = 0; i < 8; i++) {
        int idx = tid + i * 128;
        int row = idx >> 4;
        int c4  = idx & 15;
        float4 qv = ((const float4*)(Qbh + (size_t)(qtile * BM + row) * DH))[c4];
        *(float4*)((float*)sKhi + row * KSTR + c4 * 4) = qv;
    }
    __syncthreads();

    uint32_t qhi[8][4], qlo[8][4];
    {
        const float* qb = (const float*)sKhi + (warp * 16) * KSTR;
        #pragma unroll
        for (int ks = 0; ks < 8; ks++) {
            split_tf(qb[g       * KSTR + ks * 8 + j    ], qhi[ks][0], qlo[ks][0]);
            split_tf(qb[(g + 8) * KSTR + ks * 8 + j    ], qhi[ks][1], qlo[ks][1]);
            split_tf(qb[g       * KSTR + ks * 8 + j + 4], qhi[ks][2], qlo[ks][2]);
            split_tf(qb[(g + 8) * KSTR + ks * 8 + j + 4], qhi[ks][3], qlo[ks][3]);
        }
    }

    float O[8][4];
    #pragma unroll
    for (int dt = 0; dt < 8; dt++)
        #pragma unroll
        for (int e = 0; e < 4; e++) O[dt][e] = 0.f;
    float m0 = -INFINITY, m1 = -INFINITY;
    float l0 = 0.f, l1 = 0.f;

    uint32_t* pw = sKhi + (warp * 16) * KSTR;   // this warp's private P slice

    for (int k0 = 0; k0 < L; k0 += BN) {
        __syncthreads();   // prev tile: PV done reading sV & P (and Q stage done)
        // ---- load tile: split K -> (hi,lo) tf32, convert V -> tf32, ONCE ----
        #pragma unroll
        for (int i = 0; i < 8; i++) {
            int idx = tid + i * 128;
            int row = idx >> 4;
            int c4  = idx & 15;
            float4 kv = make_float4(0.f, 0.f, 0.f, 0.f);
            float4 vv = kv;
            if (k0 + row < L) {
                kv = ((const float4*)(Kbh + (size_t)(k0 + row) * DH))[c4];
                vv = ((const float4*)(Vbh + (size_t)(k0 + row) * DH))[c4];
            }
            uint4 kh, kl, vt;
            split_tf(kv.x, kh.x, kl.x); split_tf(kv.y, kh.y, kl.y);
            split_tf(kv.z, kh.z, kl.z); split_tf(kv.w, kh.w, kl.w);
            vt.x = f2tf(vv.x); vt.y = f2tf(vv.y);
            vt.z = f2tf(vv.z); vt.w = f2tf(vv.w);
            *(uint4*)(sKhi + row * KSTR + c4 * 4) = kh;
            *(uint4*)(sKlo + row * KSTR + c4 * 4) = kl;
            *(uint4*)(sV   + row * VSTR + c4 * 4) = vt;
        }
        __syncthreads();

        // ---- S = Q K^T (3-term split-tf32) ----
        float Sacc[8][4];
        #pragma unroll
        for (int nt = 0; nt < 8; nt++)
            #pragma unroll
            for (int e = 0; e < 4; e++) Sacc[nt][e] = 0.f;

        #pragma unroll
        for (int ks = 0; ks < 8; ks++) {
            #pragma unroll
            for (int nt = 0; nt < 8; nt++) {
                const int r = (nt * 8 + g) * KSTR + ks * 8 + j;
                uint32_t bhf[2] = { sKhi[r], sKhi[r + 4] };
                uint32_t blf[2] = { sKlo[r], sKlo[r + 4] };
                mma_tf32(Sacc[nt], qhi[ks], bhf, Sacc[nt]);
                mma_tf32(Sacc[nt], qhi[ks], blf, Sacc[nt]);
                mma_tf32(Sacc[nt], qlo[ks], bhf, Sacc[nt]);
            }
        }

        #pragma unroll
        for (int nt = 0; nt < 8; nt++)
            #pragma unroll
            for (int e = 0; e < 4; e++) Sacc[nt][e] *= SCALE2;

        if (k0 + BN > L) {
            #pragma unroll
            for (int nt = 0; nt < 8; nt++) {
                int col0 = k0 + nt * 8 + 2 * j;
                if (col0     >= L) { Sacc[nt][0] = -1e30f; Sacc[nt][2] = -1e30f; }
                if (col0 + 1 >= L) { Sacc[nt][1] = -1e30f; Sacc[nt][3] = -1e30f; }
            }
        }

        // ---- online softmax ----
        float cm0 = Sacc[0][0], cm1 = Sacc[0][2];
        #pragma unroll
        for (int nt = 0; nt < 8; nt++) {
            cm0 = fmaxf(cm0, fmaxf(Sacc[nt][0], Sacc[nt][1]));
            cm1 = fmaxf(cm1, fmaxf(Sacc[nt][2], Sacc[nt][3]));
        }
        cm0 = fmaxf(cm0, __shfl_xor_sync(0xffffffffu, cm0, 1));
        cm0 = fmaxf(cm0, __shfl_xor_sync(0xffffffffu, cm0, 2));
        cm1 = fmaxf(cm1, __shfl_xor_sync(0xffffffffu, cm1, 1));
        cm1 = fmaxf(cm1, __shfl_xor_sync(0xffffffffu, cm1, 2));

        float mn0 = fmaxf(m0, cm0);
        float mn1 = fmaxf(m1, cm1);
        float sc0 = ex2f(m0 - mn0);   // first tile: ex2(-inf)=0
        float sc1 = ex2f(m1 - mn1);
        m0 = mn0; m1 = mn1;
        l0 *= sc0; l1 *= sc1;
        #pragma unroll
        for (int dt = 0; dt < 8; dt++) {
            O[dt][0] *= sc0; O[dt][1] *= sc0;
            O[dt][2] *= sc1; O[dt][3] *= sc1;
        }

        __syncthreads();   // all warps finished reading sKhi/sKlo for QK

        // ---- p = ex2(s-m): write tf32 P into this warp's smem slice ----
        #pragma unroll
        for (int nt = 0; nt < 8; nt++) {
            float p0 = ex2f(Sacc[nt][0] - m0);
            float p1 = ex2f(Sacc[nt][1] - m0);
            float p2 = ex2f(Sacc[nt][2] - m1);
            float p3 = ex2f(Sacc[nt][3] - m1);
            l0 += p0 + p1;
            l1 += p2 + p3;
            *(uint2*)(pw + g       * KSTR + nt * 8 + 2 * j) =
                make_uint2(f2tf(p0), f2tf(p1));
            *(uint2*)(pw + (g + 8) * KSTR + nt * 8 + 2 * j) =
                make_uint2(f2tf(p2), f2tf(p3));
        }
        __syncwarp();

        // ---- O += P V ----
        #pragma unroll
        for (int ks = 0; ks < 8; ks++) {
            const int pr = g * KSTR + ks * 8 + j;
            uint32_t a[4] = { pw[pr], pw[pr + 8 * KSTR],
                              pw[pr + 4], pw[pr + 8 * KSTR + 4] };
            #pragma unroll
            for (int dt = 0; dt < 8; dt++) {
                uint32_t bb[2] = { sV[(ks * 8 + j    ) * VSTR + dt * 8 + g],
                                   sV[(ks * 8 + j + 4) * VSTR + dt * 8 + g] };
                mma_tf32(O[dt], a, bb, O[dt]);
            }
        }
    }

    // ---- epilogue ----
    l0 += __shfl_xor_sync(0xffffffffu, l0, 1);
    l0 += __shfl_xor_sync(0xffffffffu, l0, 2);
    l1 += __shfl_xor_sync(0xffffffffu, l1, 1);
    l1 += __shfl_xor_sync(0xffffffffu, l1, 2);
    float inv0 = 1.f / l0;
    float inv1 = 1.f / l1;

    const int qrow0 = qtile * BM + warp * 16;
    #pragma unroll
    for (int dt = 0; dt < 8; dt++) {
        int col = dt * 8 + 2 * j;
        float2 r0 = make_float2(O[dt][0] * inv0, O[dt][1] * inv0);
        float2 r1 = make_float2(O[dt][2] * inv1, O[dt][3] * inv1);
        *(float2*)(Obh + (size_t)(qrow0 + g    ) * DH + col) = r0;
        *(float2*)(Obh + (size_t)(qrow0 + g + 8) * DH + col) = r1;
    }
}

extern "C" void kernel_launch(void* const* d_in, const int* in_sizes, int n_in,
                              void* d_out, int out_size)
{
    const float* Q    = (const float*)d_in[0];
    const float* K    = (const float*)d_in[1];
    const float* V    = (const float*)d_in[2];
    const int*   lens = (const int*)  d_in[3];
    float*       out  = (float*)d_out;

    cudaFuncSetAttribute(sdpa_tf32_kernel,
                         cudaFuncAttributeMaxDynamicSharedMemorySize, SMEM_BYTES);

    dim3 grid(S_ / BM, B_ * H_);
    dim3 block(128);
    sdpa_tf32_kernel<<<grid, block, SMEM_BYTES>>>(Q, K, V, lens, out);
}

// round 6
// speedup vs baseline: 2.6113x; 1.0504x over previous
#include <cuda_runtime.h>
#include <math.h>
#include <stdint.h>

// Q,K,V: [B=4, H=8, S=2048, Dh=64] fp32 ; src_batch_lens: [4] int32
// Flash attention, warp-tiled, mma.sync m16n8k8 tf32.
// QK^T: 2-term split (qhi+qlo)*tf32(K); PV plain tf32.
// K stored fragment-packed (1 LDS.64 per B-frag); V/P row-major padded.

#define B_    4
#define H_    8
#define S_    2048
#define DH    64
#define BM    64     // q rows per CTA (16 per warp)
#define BN    64     // keys per smem tile
#define TS    64     // packed K tile stride (words per 8x8 tile)
#define VSTR  72     // sV row stride (words) — conflict-free B-frag reads
#define PSTR  68     // sP row stride (words) — conflict-free A-frag reads

#define SK_WORDS (64 * TS)          // 64 tiles (8ks x 8nt)
#define SV_WORDS (BN * VSTR)
#define SP_WORDS (BM * PSTR)        // Q stage + per-warp P slices
#define SMEM_BYTES ((SK_WORDS + SV_WORDS + SP_WORDS) * 4)

__device__ __forceinline__ float ex2f(float x) {
    float r; asm("ex2.approx.f32 %0, %1;" : "=f"(r) : "f"(x)); return r;
}
__device__ __forceinline__ uint32_t f2tf(float x) {
    uint32_t r; asm("cvt.rna.tf32.f32 %0, %1;" : "=r"(r) : "f"(x)); return r;
}
__device__ __forceinline__ void mma_tf32(float d[4], const uint32_t a[4],
                                         const uint32_t b[2], const float c[4]) {
    asm("mma.sync.aligned.m16n8k8.row.col.f32.tf32.tf32.f32 "
        "{%0,%1,%2,%3},{%4,%5,%6,%7},{%8,%9},{%10,%11,%12,%13};"
        : "=f"(d[0]), "=f"(d[1]), "=f"(d[2]), "=f"(d[3])
        : "r"(a[0]), "r"(a[1]), "r"(a[2]), "r"(a[3]),
          "r"(b[0]), "r"(b[1]),
          "f"(c[0]), "f"(c[1]), "f"(c[2]), "f"(c[3]));
}

__global__ __launch_bounds__(128)
void sdpa_tf32_kernel(const float* __restrict__ Q,
                      const float* __restrict__ K,
                      const float* __restrict__ V,
                      const int*   __restrict__ lens,
                      float*       __restrict__ out)
{
    const float SCALE2 = 0.044194173824159216f * 1.4426950408889634f; // /sqrt(512)*log2e

    const int bh    = blockIdx.y;
    const int b     = bh >> 3;
    const int qtile = blockIdx.x;
    const int tid   = threadIdx.x;
    const int warp  = tid >> 5;
    const int lane  = tid & 31;
    const int g     = lane >> 2;
    const int j     = lane & 3;
    const int L     = lens[b];

    const size_t base = (size_t)bh * S_ * DH;
    const float* Qbh = Q + base;
    const float* Kbh = K + base;
    const float* Vbh = V + base;
    float*       Obh = out + base;

    extern __shared__ uint32_t smemraw[];
    uint32_t* sK = smemraw;                 // fragment-packed K (tf32 bits)
    uint32_t* sV = sK + SK_WORDS;           // row-major V (tf32 bits)
    uint32_t* sP = sV + SV_WORDS;           // Q stage, then per-warp P slices

    // ---- stage Q tile through sP (raw float bits), split into A-frags ----
    #pragma unroll
    for (int i = 0; i < 8; i++) {
        int idx = tid + i * 128;
        int row = idx >> 4;
        int c4  = idx & 15;
        float4 qv = ((const float4*)(Qbh + (size_t)(qtile * BM + row) * DH))[c4];
        *(float4*)((float*)sP + row * PSTR + c4 * 4) = qv;
    }
    __syncthreads();

    uint32_t qhi[8][4], qlo[8][4];
    {
        const float* qb = (const float*)sP + (warp * 16) * PSTR;
        #pragma unroll
        for (int ks = 0; ks < 8; ks++) {
            float v0 = qb[g       * PSTR + ks * 8 + j    ];
            float v1 = qb[(g + 8) * PSTR + ks * 8 + j    ];
            float v2 = qb[g       * PSTR + ks * 8 + j + 4];
            float v3 = qb[(g + 8) * PSTR + ks * 8 + j + 4];
            qhi[ks][0] = f2tf(v0); qlo[ks][0] = f2tf(v0 - __uint_as_float(qhi[ks][0]));
            qhi[ks][1] = f2tf(v1); qlo[ks][1] = f2tf(v1 - __uint_as_float(qhi[ks][1]));
            qhi[ks][2] = f2tf(v2); qlo[ks][2] = f2tf(v2 - __uint_as_float(qhi[ks][2]));
            qhi[ks][3] = f2tf(v3); qlo[ks][3] = f2tf(v3 - __uint_as_float(qhi[ks][3]));
        }
    }

    float O[8][4];
    #pragma unroll
    for (int dt = 0; dt < 8; dt++)
        #pragma unroll
        for (int e = 0; e < 4; e++) O[dt][e] = 0.f;
    float m0 = -INFINITY, m1 = -INFINITY;
    float l0 = 0.f, l1 = 0.f;

    uint32_t* pw = sP + (warp * 16) * PSTR;   // this warp's private P slice

    for (int k0 = 0; k0 < L; k0 += BN) {
        __syncthreads();   // prev tile: QK done with sK, PV done with sV/sP

        // ---- load K fragment-packed (single tf32) ----
        #pragma unroll
        for (int it = 0; it < 4; it++) {
            int unit = tid + it * 128;       // 0..511
            int ks = unit >> 6;              // 0..7
            int r  = unit & 63;              // key row in tile
            float4 a0 = make_float4(0.f, 0.f, 0.f, 0.f);
            float4 a1 = a0;
            if (k0 + r < L) {
                const float4* kp = (const float4*)(Kbh + (size_t)(k0 + r) * DH + ks * 8);
                a0 = kp[0]; a1 = kp[1];
            }
            // words [g*8..g*8+7] = {c0,c4,c1,c5,c2,c6,c3,c7}
            uint4 w0 = make_uint4(f2tf(a0.x), f2tf(a1.x), f2tf(a0.y), f2tf(a1.y));
            uint4 w1 = make_uint4(f2tf(a0.z), f2tf(a1.z), f2tf(a0.w), f2tf(a1.w));
            uint32_t* dst = sK + ((ks * 8 + (r >> 3)) * TS + (r & 7) * 8);
            *(uint4*)dst       = w0;
            *(uint4*)(dst + 4) = w1;
        }
        // ---- load V row-major tf32 ----
        #pragma unroll
        for (int i = 0; i < 8; i++) {
            int idx = tid + i * 128;
            int row = idx >> 4;
            int c4  = idx & 15;
            float4 vv = make_float4(0.f, 0.f, 0.f, 0.f);
            if (k0 + row < L)
                vv = ((const float4*)(Vbh + (size_t)(k0 + row) * DH))[c4];
            uint4 vt = make_uint4(f2tf(vv.x), f2tf(vv.y), f2tf(vv.z), f2tf(vv.w));
            *(uint4*)(sV + row * VSTR + c4 * 4) = vt;
        }
        __syncthreads();

        // ---- S = Q K^T : 2 MMAs per (ks,nt), B via one LDS.64 ----
        float Sacc[8][4];
        #pragma unroll
        for (int nt = 0; nt < 8; nt++)
            #pragma unroll
            for (int e = 0; e < 4; e++) Sacc[nt][e] = 0.f;

        const uint2* sKp = (const uint2*)sK;
        #pragma unroll
        for (int ks = 0; ks < 8; ks++) {
            #pragma unroll
            for (int nt = 0; nt < 8; nt++) {
                uint2 bv = sKp[(ks * 8 + nt) * (TS / 2) + lane];
                uint32_t bb[2] = { bv.x, bv.y };
                mma_tf32(Sacc[nt], qhi[ks], bb, Sacc[nt]);
                mma_tf32(Sacc[nt], qlo[ks], bb, Sacc[nt]);
            }
        }

        #pragma unroll
        for (int nt = 0; nt < 8; nt++)
            #pragma unroll
            for (int e = 0; e < 4; e++) Sacc[nt][e] *= SCALE2;

        if (k0 + BN > L) {
            #pragma unroll
            for (int nt = 0; nt < 8; nt++) {
                int col0 = k0 + nt * 8 + 2 * j;
                if (col0     >= L) { Sacc[nt][0] = -1e30f; Sacc[nt][2] = -1e30f; }
                if (col0 + 1 >= L) { Sacc[nt][1] = -1e30f; Sacc[nt][3] = -1e30f; }
            }
        }

        // ---- online softmax ----
        float cm0 = Sacc[0][0], cm1 = Sacc[0][2];
        #pragma unroll
        for (int nt = 0; nt < 8; nt++) {
            cm0 = fmaxf(cm0, fmaxf(Sacc[nt][0], Sacc[nt][1]));
            cm1 = fmaxf(cm1, fmaxf(Sacc[nt][2], Sacc[nt][3]));
        }
        cm0 = fmaxf(cm0, __shfl_xor_sync(0xffffffffu, cm0, 1));
        cm0 = fmaxf(cm0, __shfl_xor_sync(0xffffffffu, cm0, 2));
        cm1 = fmaxf(cm1, __shfl_xor_sync(0xffffffffu, cm1, 1));
        cm1 = fmaxf(cm1, __shfl_xor_sync(0xffffffffu, cm1, 2));

        float mn0 = fmaxf(m0, cm0);
        float mn1 = fmaxf(m1, cm1);
        float sc0 = ex2f(m0 - mn0);   // first tile: ex2(-inf)=0
        float sc1 = ex2f(m1 - mn1);
        m0 = mn0; m1 = mn1;
        l0 *= sc0; l1 *= sc1;
        #pragma unroll
        for (int dt = 0; dt < 8; dt++) {
            O[dt][0] *= sc0; O[dt][1] *= sc0;
            O[dt][2] *= sc1; O[dt][3] *= sc1;
        }

        // ---- p = ex2(s-m) -> warp-private P slice (tf32 bits) ----
        #pragma unroll
        for (int nt = 0; nt < 8; nt++) {
            float p0 = ex2f(Sacc[nt][0] - m0);
            float p1 = ex2f(Sacc[nt][1] - m0);
            float p2 = ex2f(Sacc[nt][2] - m1);
            float p3 = ex2f(Sacc[nt][3] - m1);
            l0 += p0 + p1;
            l1 += p2 + p3;
            *(uint2*)(pw + g       * PSTR + nt * 8 + 2 * j) =
                make_uint2(f2tf(p0), f2tf(p1));
            *(uint2*)(pw + (g + 8) * PSTR + nt * 8 + 2 * j) =
                make_uint2(f2tf(p2), f2tf(p3));
        }
        __syncwarp();

        // ---- O += P V ----
        #pragma unroll
        for (int ks = 0; ks < 8; ks++) {
            const int pr = g * PSTR + ks * 8 + j;
            uint32_t a[4] = { pw[pr], pw[pr + 8 * PSTR],
                              pw[pr + 4], pw[pr + 8 * PSTR + 4] };
            #pragma unroll
            for (int dt = 0; dt < 8; dt++) {
                uint32_t bb[2] = { sV[(ks * 8 + j    ) * VSTR + dt * 8 + g],
                                   sV[(ks * 8 + j + 4) * VSTR + dt * 8 + g] };
                mma_tf32(O[dt], a, bb, O[dt]);
            }
        }
    }

    // ---- epilogue ----
    l0 += __shfl_xor_sync(0xffffffffu, l0, 1);
    l0 += __shfl_xor_sync(0xffffffffu, l0, 2);
    l1 += __shfl_xor_sync(0xffffffffu, l1, 1);
    l1 += __shfl_xor_sync(0xffffffffu, l1, 2);
    float inv0 = 1.f / l0;
    float inv1 = 1.f / l1;

    const int qrow0 = qtile * BM + warp * 16;
    #pragma unroll
    for (int dt = 0; dt < 8; dt++) {
        int col = dt * 8 + 2 * j;
        float2 r0 = make_float2(O[dt][0] * inv0, O[dt][1] * inv0);
        float2 r1 = make_float2(O[dt][2] * inv1, O[dt][3] * inv1);
        *(float2*)(Obh + (size_t)(qrow0 + g    ) * DH + col) = r0;
        *(float2*)(Obh + (size_t)(qrow0 + g + 8) * DH + col) = r1;
    }
}

extern "C" void kernel_launch(void* const* d_in, const int* in_sizes, int n_in,
                              void* d_out, int out_size)
{
    const float* Q    = (const float*)d_in[0];
    const float* K    = (const float*)d_in[1];
    const float* V    = (const float*)d_in[2];
    const int*   lens = (const int*)  d_in[3];
    float*       out  = (float*)d_out;

    cudaFuncSetAttribute(sdpa_tf32_kernel,
                         cudaFuncAttributeMaxDynamicSharedMemorySize, SMEM_BYTES);

    dim3 grid(S_ / BM, B_ * H_);
    dim3 block(128);
    sdpa_tf32_kernel<<<grid, block, SMEM_BYTES>>>(Q, K, V, lens, out);
}

// round 7
// speedup vs baseline: 3.4434x; 1.3187x over previous
#include <cuda_runtime.h>
#include <math.h>
#include <stdint.h>

// Q,K,V: [B=4, H=8, S=2048, Dh=64] fp32 ; src_batch_lens: [4] int32
// Flash attention, warp-tiled mma.sync m16n8k8 tf32, cp.async 2-stage pipeline.
// K,V consumed as RAW fp32 bits (HMMA truncates to tf32); Q split 2-term rna;
// l accumulated from truncated p (self-normalizing); V truncation mean-bias
// corrected by (1+2^-11) at the end.

#define B_    4
#define H_    8
#define S_    2048
#define DH    64
#define BM    64     // q rows per CTA (16 per warp)
#define BN    64     // keys per smem tile
#define KSTR  68     // sK row stride (words): B-frag bank = 4g+j, distinct
#define VSTR  72     // sV row stride (words): B-frag bank = 8j+g, distinct
#define PSTR  68     // sP row stride (words)

#define KBUF  (BN * KSTR)
#define VBUF  (BN * VSTR)
#define SMEM_WORDS (2 * KBUF + 2 * VBUF + BM * PSTR)
#define SMEM_BYTES (SMEM_WORDS * 4)

__device__ __forceinline__ float ex2f(float x) {
    float r; asm("ex2.approx.f32 %0, %1;" : "=f"(r) : "f"(x)); return r;
}
__device__ __forceinline__ uint32_t f2tf(float x) {
    uint32_t r; asm("cvt.rna.tf32.f32 %0, %1;" : "=r"(r) : "f"(x)); return r;
}
__device__ __forceinline__ uint32_t s2u(const void* p) {
    uint32_t r;
    asm("{ .reg .u64 t; cvta.to.shared.u64 t, %1; cvt.u32.u64 %0, t; }"
        : "=r"(r) : "l"(p));
    return r;
}
__device__ __forceinline__ void cpa16(uint32_t dst, const void* src, int srcsz) {
    asm volatile("cp.async.cg.shared.global [%0], [%1], 16, %2;"
                 :: "r"(dst), "l"(src), "r"(srcsz));
}
#define CP_COMMIT() asm volatile("cp.async.commit_group;")
#define CP_WAIT0()  asm volatile("cp.async.wait_group 0;" ::: "memory")

__device__ __forceinline__ void mma_tf32(float d[4], const uint32_t a[4],
                                         const uint32_t b[2], const float c[4]) {
    asm("mma.sync.aligned.m16n8k8.row.col.f32.tf32.tf32.f32 "
        "{%0,%1,%2,%3},{%4,%5,%6,%7},{%8,%9},{%10,%11,%12,%13};"
        : "=f"(d[0]), "=f"(d[1]), "=f"(d[2]), "=f"(d[3])
        : "r"(a[0]), "r"(a[1]), "r"(a[2]), "r"(a[3]),
          "r"(b[0]), "r"(b[1]),
          "f"(c[0]), "f"(c[1]), "f"(c[2]), "f"(c[3]));
}

__global__ __launch_bounds__(128)
void sdpa_tf32_kernel(const float* __restrict__ Q,
                      const float* __restrict__ K,
                      const float* __restrict__ V,
                      const int*   __restrict__ lens,
                      float*       __restrict__ out)
{
    const float SCALE2 = 0.044194173824159216f * 1.4426950408889634f; // /sqrt(512)*log2e

    const int bh    = blockIdx.y;
    const int b     = bh >> 3;
    const int qtile = blockIdx.x;
    const int tid   = threadIdx.x;
    const int warp  = tid >> 5;
    const int lane  = tid & 31;
    const int g     = lane >> 2;
    const int j     = lane & 3;
    const int L     = lens[b];

    const size_t base = (size_t)bh * S_ * DH;
    const float* Qbh = Q + base;
    const float* Kbh = K + base;
    const float* Vbh = V + base;
    float*       Obh = out + base;

    extern __shared__ uint32_t smemraw[];
    uint32_t* sK0 = smemraw;             // raw fp32 K, buffer 0
    uint32_t* sK1 = sK0 + KBUF;          // buffer 1
    uint32_t* sV0 = sK1 + KBUF;
    uint32_t* sV1 = sV0 + VBUF;
    uint32_t* sP  = sV1 + VBUF;          // Q stage, then per-warp P slices

    const uint32_t uK0 = s2u(sK0), uK1 = s2u(sK1);
    const uint32_t uV0 = s2u(sV0), uV1 = s2u(sV1);

    const int ntiles = (L + BN - 1) / BN;

    // row/col this thread copies (8 chunks of 16B each for K and V)
    const int crow = tid >> 4;       // base row, +8 per iteration
    const int cc4  = tid & 15;       // float4 column

    // ---- prologue: issue tile 0 ----
    {
        #pragma unroll
        for (int i = 0; i < 8; i++) {
            int row = crow + i * 8;
            int gr  = row;                      // k0 = 0
            int ok  = gr < L ? 16 : 0;
            int cr  = gr < L ? gr : 0;
            cpa16(uK0 + (row * KSTR + cc4 * 4) * 4, Kbh + (size_t)cr * DH + cc4 * 4, ok);
            cpa16(uV0 + (row * VSTR + cc4 * 4) * 4, Vbh + (size_t)cr * DH + cc4 * 4, ok);
        }
        CP_COMMIT();
    }

    // ---- stage Q tile through sP, split into 2-term rna A-frags ----
    #pragma unroll
    for (int i = 0; i < 8; i++) {
        int row = crow + i * 8;
        float4 qv = ((const float4*)(Qbh + (size_t)(qtile * BM + row) * DH))[cc4];
        *(float4*)((float*)sP + row * PSTR + cc4 * 4) = qv;
    }
    __syncthreads();

    uint32_t qhi[8][4], qlo[8][4];
    {
        const float* qb = (const float*)sP + (warp * 16) * PSTR;
        #pragma unroll
        for (int ks = 0; ks < 8; ks++) {
            float v0 = qb[g       * PSTR + ks * 8 + j    ];
            float v1 = qb[(g + 8) * PSTR + ks * 8 + j    ];
            float v2 = qb[g       * PSTR + ks * 8 + j + 4];
            float v3 = qb[(g + 8) * PSTR + ks * 8 + j + 4];
            qhi[ks][0] = f2tf(v0); qlo[ks][0] = f2tf(v0 - __uint_as_float(qhi[ks][0]));
            qhi[ks][1] = f2tf(v1); qlo[ks][1] = f2tf(v1 - __uint_as_float(qhi[ks][1]));
            qhi[ks][2] = f2tf(v2); qlo[ks][2] = f2tf(v2 - __uint_as_float(qhi[ks][2]));
            qhi[ks][3] = f2tf(v3); qlo[ks][3] = f2tf(v3 - __uint_as_float(qhi[ks][3]));
        }
    }

    float O[8][4];
    #pragma unroll
    for (int dt = 0; dt < 8; dt++)
        #pragma unroll
        for (int e = 0; e < 4; e++) O[dt][e] = 0.f;
    float m0 = -INFINITY, m1 = -INFINITY;
    float l0 = 0.f, l1 = 0.f;

    uint32_t* pw = sP + (warp * 16) * PSTR;   // warp-private P slice

    for (int t = 0; t < ntiles; t++) {
        const int k0 = t * BN;
        const uint32_t* sK = (t & 1) ? sK1 : sK0;
        const uint32_t* sV = (t & 1) ? sV1 : sV0;

        CP_WAIT0();          // tile t resident (this thread's copies)
        __syncthreads();     // everyone's copies visible; prev compute done

        // issue tile t+1 into the other buffer
        if (t + 1 < ntiles) {
            const uint32_t uKn = (t & 1) ? uK0 : uK1;
            const uint32_t uVn = (t & 1) ? uV0 : uV1;
            const int kn = k0 + BN;
            #pragma unroll
            for (int i = 0; i < 8; i++) {
                int row = crow + i * 8;
                int gr  = kn + row;
                int ok  = gr < L ? 16 : 0;
                int cr  = gr < L ? gr : 0;
                cpa16(uKn + (row * KSTR + cc4 * 4) * 4, Kbh + (size_t)cr * DH + cc4 * 4, ok);
                cpa16(uVn + (row * VSTR + cc4 * 4) * 4, Vbh + (size_t)cr * DH + cc4 * 4, ok);
            }
        }
        CP_COMMIT();         // commit (possibly empty) group

        // ---- S = Q K^T : raw K bits as tf32 B-operands ----
        float Sacc[8][4];
        #pragma unroll
        for (int nt = 0; nt < 8; nt++)
            #pragma unroll
            for (int e = 0; e < 4; e++) Sacc[nt][e] = 0.f;

        #pragma unroll
        for (int ks = 0; ks < 8; ks++) {
            #pragma unroll
            for (int nt = 0; nt < 8; nt++) {
                const int r = (nt * 8 + g) * KSTR + ks * 8 + j;
                uint32_t bb[2] = { sK[r], sK[r + 4] };
                mma_tf32(Sacc[nt], qhi[ks], bb, Sacc[nt]);
                mma_tf32(Sacc[nt], qlo[ks], bb, Sacc[nt]);
            }
        }

        #pragma unroll
        for (int nt = 0; nt < 8; nt++)
            #pragma unroll
            for (int e = 0; e < 4; e++) Sacc[nt][e] *= SCALE2;

        if (k0 + BN > L) {
            #pragma unroll
            for (int nt = 0; nt < 8; nt++) {
                int col0 = k0 + nt * 8 + 2 * j;
                if (col0     >= L) { Sacc[nt][0] = -1e30f; Sacc[nt][2] = -1e30f; }
                if (col0 + 1 >= L) { Sacc[nt][1] = -1e30f; Sacc[nt][3] = -1e30f; }
            }
        }

        // ---- online softmax ----
        float cm0 = Sacc[0][0], cm1 = Sacc[0][2];
        #pragma unroll
        for (int nt = 0; nt < 8; nt++) {
            cm0 = fmaxf(cm0, fmaxf(Sacc[nt][0], Sacc[nt][1]));
            cm1 = fmaxf(cm1, fmaxf(Sacc[nt][2], Sacc[nt][3]));
        }
        cm0 = fmaxf(cm0, __shfl_xor_sync(0xffffffffu, cm0, 1));
        cm0 = fmaxf(cm0, __shfl_xor_sync(0xffffffffu, cm0, 2));
        cm1 = fmaxf(cm1, __shfl_xor_sync(0xffffffffu, cm1, 1));
        cm1 = fmaxf(cm1, __shfl_xor_sync(0xffffffffu, cm1, 2));

        float mn0 = fmaxf(m0, cm0);
        float mn1 = fmaxf(m1, cm1);
        float sc0 = ex2f(m0 - mn0);   // first tile: ex2(-inf)=0
        float sc1 = ex2f(m1 - mn1);
        m0 = mn0; m1 = mn1;
        l0 *= sc0; l1 *= sc1;
        #pragma unroll
        for (int dt = 0; dt < 8; dt++) {
            O[dt][0] *= sc0; O[dt][1] *= sc0;
            O[dt][2] *= sc1; O[dt][3] *= sc1;
        }

        // ---- p = ex2(s-m), truncate to tf32 bits; l from TRUNCATED p ----
        #pragma unroll
        for (int nt = 0; nt < 8; nt++) {
            uint32_t t0 = __float_as_uint(ex2f(Sacc[nt][0] - m0)) & 0xFFFFE000u;
            uint32_t t1 = __float_as_uint(ex2f(Sacc[nt][1] - m0)) & 0xFFFFE000u;
            uint32_t t2 = __float_as_uint(ex2f(Sacc[nt][2] - m1)) & 0xFFFFE000u;
            uint32_t t3 = __float_as_uint(ex2f(Sacc[nt][3] - m1)) & 0xFFFFE000u;
            l0 += __uint_as_float(t0) + __uint_as_float(t1);
            l1 += __uint_as_float(t2) + __uint_as_float(t3);
            *(uint2*)(pw + g       * PSTR + nt * 8 + 2 * j) = make_uint2(t0, t1);
            *(uint2*)(pw + (g + 8) * PSTR + nt * 8 + 2 * j) = make_uint2(t2, t3);
        }
        __syncwarp();

        // ---- O += P V (raw V bits as tf32 B-operands) ----
        #pragma unroll
        for (int ks = 0; ks < 8; ks++) {
            const int pr = g * PSTR + ks * 8 + j;
            uint32_t a[4] = { pw[pr], pw[pr + 8 * PSTR],
                              pw[pr + 4], pw[pr + 8 * PSTR + 4] };
            #pragma unroll
            for (int dt = 0; dt < 8; dt++) {
                uint32_t bb[2] = { sV[(ks * 8 + j    ) * VSTR + dt * 8 + g],
                                   sV[(ks * 8 + j + 4) * VSTR + dt * 8 + g] };
                mma_tf32(O[dt], a, bb, O[dt]);
            }
        }
    }

    // ---- epilogue: V-truncation mean bias corrected by (1+2^-11) ----
    l0 += __shfl_xor_sync(0xffffffffu, l0, 1);
    l0 += __shfl_xor_sync(0xffffffffu, l0, 2);
    l1 += __shfl_xor_sync(0xffffffffu, l1, 1);
    l1 += __shfl_xor_sync(0xffffffffu, l1, 2);
    const float BIAS = 1.00048828125f;
    float inv0 = BIAS / l0;
    float inv1 = BIAS / l1;

    const int qrow0 = qtile * BM + warp * 16;
    #pragma unroll
    for (int dt = 0; dt < 8; dt++) {
        int col = dt * 8 + 2 * j;
        float2 r0 = make_float2(O[dt][0] * inv0, O[dt][1] * inv0);
        float2 r1 = make_float2(O[dt][2] * inv1, O[dt][3] * inv1);
        *(float2*)(Obh + (size_t)(qrow0 + g    ) * DH + col) = r0;
        *(float2*)(Obh + (size_t)(qrow0 + g + 8) * DH + col) = r1;
    }
}

extern "C" void kernel_launch(void* const* d_in, const int* in_sizes, int n_in,
                              void* d_out, int out_size)
{
    const float* Q    = (const float*)d_in[0];
    const float* K    = (const float*)d_in[1];
    const float* V    = (const float*)d_in[2];
    const int*   lens = (const int*)  d_in[3];
    float*       out  = (float*)d_out;

    cudaFuncSetAttribute(sdpa_tf32_kernel,
                         cudaFuncAttributeMaxDynamicSharedMemorySize, SMEM_BYTES);

    dim3 grid(S_ / BM, B_ * H_);
    dim3 block(128);
    sdpa_tf32_kernel<<<grid, block, SMEM_BYTES>>>(Q, K, V, lens, out);
}

// round 8
// speedup vs baseline: 3.4519x; 1.0025x over previous
#include <cuda_runtime.h>
#include <math.h>
#include <stdint.h>

// Q,K,V: [B=4, H=8, S=2048, Dh=64] fp32 ; src_batch_lens: [4] int32
// Flash attention, warp-tiled mma.sync m16n8k8 tf32, cp.async 2-stage pipeline.
// K,V consumed as RAW fp32 bits (HMMA truncates to tf32); Q split 2-term rna;
// l accumulated from truncated p (self-normalizing); V truncation mean-bias
// corrected by (1+2^-11) at the end.

#define B_    4
#define H_    8
#define S_    2048
#define DH    64
#define BM    64     // q rows per CTA (16 per warp)
#define BN    64     // keys per smem tile
#define KSTR  68     // sK row stride (words): B-frag bank = 4g+j, distinct
#define VSTR  72     // sV row stride (words): B-frag bank = 8j+g, distinct
#define PSTR  68     // sP row stride (words)

#define KBUF  (BN * KSTR)
#define VBUF  (BN * VSTR)
#define SMEM_WORDS (2 * KBUF + 2 * VBUF + BM * PSTR)
#define SMEM_BYTES (SMEM_WORDS * 4)

__device__ __forceinline__ float ex2f(float x) {
    float r; asm("ex2.approx.f32 %0, %1;" : "=f"(r) : "f"(x)); return r;
}
__device__ __forceinline__ uint32_t f2tf(float x) {
    uint32_t r; asm("cvt.rna.tf32.f32 %0, %1;" : "=r"(r) : "f"(x)); return r;
}
__device__ __forceinline__ uint32_t s2u(const void* p) {
    uint32_t r;
    asm("{ .reg .u64 t; cvta.to.shared.u64 t, %1; cvt.u32.u64 %0, t; }"
        : "=r"(r) : "l"(p));
    return r;
}
__device__ __forceinline__ void cpa16(uint32_t dst, const void* src, int srcsz) {
    asm volatile("cp.async.cg.shared.global [%0], [%1], 16, %2;"
                 :: "r"(dst), "l"(src), "r"(srcsz));
}
#define CP_COMMIT() asm volatile("cp.async.commit_group;")
#define CP_WAIT0()  asm volatile("cp.async.wait_group 0;" ::: "memory")

__device__ __forceinline__ void mma_tf32(float d[4], const uint32_t a[4],
                                         const uint32_t b[2], const float c[4]) {
    asm("mma.sync.aligned.m16n8k8.row.col.f32.tf32.tf32.f32 "
        "{%0,%1,%2,%3},{%4,%5,%6,%7},{%8,%9},{%10,%11,%12,%13};"
        : "=f"(d[0]), "=f"(d[1]), "=f"(d[2]), "=f"(d[3])
        : "r"(a[0]), "r"(a[1]), "r"(a[2]), "r"(a[3]),
          "r"(b[0]), "r"(b[1]),
          "f"(c[0]), "f"(c[1]), "f"(c[2]), "f"(c[3]));
}

__global__ __launch_bounds__(128)
void sdpa_tf32_kernel(const float* __restrict__ Q,
                      const float* __restrict__ K,
                      const float* __restrict__ V,
                      const int*   __restrict__ lens,
                      float*       __restrict__ out)
{
    const float SCALE2 = 0.044194173824159216f * 1.4426950408889634f; // /sqrt(512)*log2e

    const int bh    = blockIdx.y;
    const int b     = bh >> 3;
    const int qtile = blockIdx.x;
    const int tid   = threadIdx.x;
    const int warp  = tid >> 5;
    const int lane  = tid & 31;
    const int g     = lane >> 2;
    const int j     = lane & 3;
    const int L     = lens[b];

    const size_t base = (size_t)bh * S_ * DH;
    const float* Qbh = Q + base;
    const float* Kbh = K + base;
    const float* Vbh = V + base;
    float*       Obh = out + base;

    extern __shared__ uint32_t smemraw[];
    uint32_t* sK0 = smemraw;             // raw fp32 K, buffer 0
    uint32_t* sK1 = sK0 + KBUF;          // buffer 1
    uint32_t* sV0 = sK1 + KBUF;
    uint32_t* sV1 = sV0 + VBUF;
    uint32_t* sP  = sV1 + VBUF;          // Q stage, then per-warp P slices

    const uint32_t uK0 = s2u(sK0), uK1 = s2u(sK1);
    const uint32_t uV0 = s2u(sV0), uV1 = s2u(sV1);

    const int ntiles = (L + BN - 1) / BN;

    // row/col this thread copies (8 chunks of 16B each for K and V)
    const int crow = tid >> 4;       // base row, +8 per iteration
    const int cc4  = tid & 15;       // float4 column

    // ---- prologue: issue tile 0 ----
    {
        #pragma unroll
        for (int i = 0; i < 8; i++) {
            int row = crow + i * 8;
            int gr  = row;                      // k0 = 0
            int ok  = gr < L ? 16 : 0;
            int cr  = gr < L ? gr : 0;
            cpa16(uK0 + (row * KSTR + cc4 * 4) * 4, Kbh + (size_t)cr * DH + cc4 * 4, ok);
            cpa16(uV0 + (row * VSTR + cc4 * 4) * 4, Vbh + (size_t)cr * DH + cc4 * 4, ok);
        }
        CP_COMMIT();
    }

    // ---- stage Q tile through sP, split into 2-term rna A-frags ----
    #pragma unroll
    for (int i = 0; i < 8; i++) {
        int row = crow + i * 8;
        float4 qv = ((const float4*)(Qbh + (size_t)(qtile * BM + row) * DH))[cc4];
        *(float4*)((float*)sP + row * PSTR + cc4 * 4) = qv;
    }
    __syncthreads();

    uint32_t qhi[8][4], qlo[8][4];
    {
        const float* qb = (const float*)sP + (warp * 16) * PSTR;
        #pragma unroll
        for (int ks = 0; ks < 8; ks++) {
            float v0 = qb[g       * PSTR + ks * 8 + j    ];
            float v1 = qb[(g + 8) * PSTR + ks * 8 + j    ];
            float v2 = qb[g       * PSTR + ks * 8 + j + 4];
            float v3 = qb[(g + 8) * PSTR + ks * 8 + j + 4];
            qhi[ks][0] = f2tf(v0); qlo[ks][0] = f2tf(v0 - __uint_as_float(qhi[ks][0]));
            qhi[ks][1] = f2tf(v1); qlo[ks][1] = f2tf(v1 - __uint_as_float(qhi[ks][1]));
            qhi[ks][2] = f2tf(v2); qlo[ks][2] = f2tf(v2 - __uint_as_float(qhi[ks][2]));
            qhi[ks][3] = f2tf(v3); qlo[ks][3] = f2tf(v3 - __uint_as_float(qhi[ks][3]));
        }
    }

    float O[8][4];
    #pragma unroll
    for (int dt = 0; dt < 8; dt++)
        #pragma unroll
        for (int e = 0; e < 4; e++) O[dt][e] = 0.f;
    float m0 = -INFINITY, m1 = -INFINITY;
    float l0 = 0.f, l1 = 0.f;

    uint32_t* pw = sP + (warp * 16) * PSTR;   // warp-private P slice

    for (int t = 0; t < ntiles; t++) {
        const int k0 = t * BN;
        const uint32_t* sK = (t & 1) ? sK1 : sK0;
        const uint32_t* sV = (t & 1) ? sV1 : sV0;

        CP_WAIT0();          // tile t resident (this thread's copies)
        __syncthreads();     // everyone's copies visible; prev compute done

        // issue tile t+1 into the other buffer
        if (t + 1 < ntiles) {
            const uint32_t uKn = (t & 1) ? uK0 : uK1;
            const uint32_t uVn = (t & 1) ? uV0 : uV1;
            const int kn = k0 + BN;
            #pragma unroll
            for (int i = 0; i < 8; i++) {
                int row = crow + i * 8;
                int gr  = kn + row;
                int ok  = gr < L ? 16 : 0;
                int cr  = gr < L ? gr : 0;
                cpa16(uKn + (row * KSTR + cc4 * 4) * 4, Kbh + (size_t)cr * DH + cc4 * 4, ok);
                cpa16(uVn + (row * VSTR + cc4 * 4) * 4, Vbh + (size_t)cr * DH + cc4 * 4, ok);
            }
        }
        CP_COMMIT();         // commit (possibly empty) group

        // ---- S = Q K^T : raw K bits as tf32 B-operands ----
        float Sacc[8][4];
        #pragma unroll
        for (int nt = 0; nt < 8; nt++)
            #pragma unroll
            for (int e = 0; e < 4; e++) Sacc[nt][e] = 0.f;

        #pragma unroll
        for (int ks = 0; ks < 8; ks++) {
            #pragma unroll
            for (int nt = 0; nt < 8; nt++) {
                const int r = (nt * 8 + g) * KSTR + ks * 8 + j;
                uint32_t bb[2] = { sK[r], sK[r + 4] };
                mma_tf32(Sacc[nt], qhi[ks], bb, Sacc[nt]);
                mma_tf32(Sacc[nt], qlo[ks], bb, Sacc[nt]);
            }
        }

        #pragma unroll
        for (int nt = 0; nt < 8; nt++)
            #pragma unroll
            for (int e = 0; e < 4; e++) Sacc[nt][e] *= SCALE2;

        if (k0 + BN > L) {
            #pragma unroll
            for (int nt = 0; nt < 8; nt++) {
                int col0 = k0 + nt * 8 + 2 * j;
                if (col0     >= L) { Sacc[nt][0] = -1e30f; Sacc[nt][2] = -1e30f; }
                if (col0 + 1 >= L) { Sacc[nt][1] = -1e30f; Sacc[nt][3] = -1e30f; }
            }
        }

        // ---- online softmax ----
        float cm0 = Sacc[0][0], cm1 = Sacc[0][2];
        #pragma unroll
        for (int nt = 0; nt < 8; nt++) {
            cm0 = fmaxf(cm0, fmaxf(Sacc[nt][0], Sacc[nt][1]));
            cm1 = fmaxf(cm1, fmaxf(Sacc[nt][2], Sacc[nt][3]));
        }
        cm0 = fmaxf(cm0, __shfl_xor_sync(0xffffffffu, cm0, 1));
        cm0 = fmaxf(cm0, __shfl_xor_sync(0xffffffffu, cm0, 2));
        cm1 = fmaxf(cm1, __shfl_xor_sync(0xffffffffu, cm1, 1));
        cm1 = fmaxf(cm1, __shfl_xor_sync(0xffffffffu, cm1, 2));

        float mn0 = fmaxf(m0, cm0);
        float mn1 = fmaxf(m1, cm1);
        float sc0 = ex2f(m0 - mn0);   // first tile: ex2(-inf)=0
        float sc1 = ex2f(m1 - mn1);
        m0 = mn0; m1 = mn1;
        l0 *= sc0; l1 *= sc1;
        #pragma unroll
        for (int dt = 0; dt < 8; dt++) {
            O[dt][0] *= sc0; O[dt][1] *= sc0;
            O[dt][2] *= sc1; O[dt][3] *= sc1;
        }

        // ---- p = ex2(s-m), truncate to tf32 bits; l from TRUNCATED p ----
        #pragma unroll
        for (int nt = 0; nt < 8; nt++) {
            uint32_t t0 = __float_as_uint(ex2f(Sacc[nt][0] - m0)) & 0xFFFFE000u;
            uint32_t t1 = __float_as_uint(ex2f(Sacc[nt][1] - m0)) & 0xFFFFE000u;
            uint32_t t2 = __float_as_uint(ex2f(Sacc[nt][2] - m1)) & 0xFFFFE000u;
            uint32_t t3 = __float_as_uint(ex2f(Sacc[nt][3] - m1)) & 0xFFFFE000u;
            l0 += __uint_as_float(t0) + __uint_as_float(t1);
            l1 += __uint_as_float(t2) + __uint_as_float(t3);
            *(uint2*)(pw + g       * PSTR + nt * 8 + 2 * j) = make_uint2(t0, t1);
            *(uint2*)(pw + (g + 8) * PSTR + nt * 8 + 2 * j) = make_uint2(t2, t3);
        }
        __syncwarp();

        // ---- O += P V (raw V bits as tf32 B-operands) ----
        #pragma unroll
        for (int ks = 0; ks < 8; ks++) {
            const int pr = g * PSTR + ks * 8 + j;
            uint32_t a[4] = { pw[pr], pw[pr + 8 * PSTR],
                              pw[pr + 4], pw[pr + 8 * PSTR + 4] };
            #pragma unroll
            for (int dt = 0; dt < 8; dt++) {
                uint32_t bb[2] = { sV[(ks * 8 + j    ) * VSTR + dt * 8 + g],
                                   sV[(ks * 8 + j + 4) * VSTR + dt * 8 + g] };
                mma_tf32(O[dt], a, bb, O[dt]);
            }
        }
    }

    // ---- epilogue: V-truncation mean bias corrected by (1+2^-11) ----
    l0 += __shfl_xor_sync(0xffffffffu, l0, 1);
    l0 += __shfl_xor_sync(0xffffffffu, l0, 2);
    l1 += __shfl_xor_sync(0xffffffffu, l1, 1);
    l1 += __shfl_xor_sync(0xffffffffu, l1, 2);
    const float BIAS = 1.00048828125f;
    float inv0 = BIAS / l0;
    float inv1 = BIAS / l1;

    const int qrow0 = qtile * BM + warp * 16;
    #pragma unroll
    for (int dt = 0; dt < 8; dt++) {
        int col = dt * 8 + 2 * j;
        float2 r0 = make_float2(O[dt][0] * inv0, O[dt][1] * inv0);
        float2 r1 = make_float2(O[dt][2] * inv1, O[dt][3] * inv1);
        *(float2*)(Obh + (size_t)(qrow0 + g    ) * DH + col) = r0;
        *(float2*)(Obh + (size_t)(qrow0 + g + 8) * DH + col) = r1;
    }
}

extern "C" void kernel_launch(void* const* d_in, const int* in_sizes, int n_in,
                              void* d_out, int out_size)
{
    const float* Q    = (const float*)d_in[0];
    const float* K    = (const float*)d_in[1];
    const float* V    = (const float*)d_in[2];
    const int*   lens = (const int*)  d_in[3];
    float*       out  = (float*)d_out;

    cudaFuncSetAttribute(sdpa_tf32_kernel,
                         cudaFuncAttributeMaxDynamicSharedMemorySize, SMEM_BYTES);

    dim3 grid(S_ / BM, B_ * H_);
    dim3 block(128);
    sdpa_tf32_kernel<<<grid, block, SMEM_BYTES>>>(Q, K, V, lens, out);
}